// round 8
// baseline (speedup 1.0000x reference)
#include <cuda_runtime.h>

#define NPTS 1024

// ---------------- packed f32x2 helpers (Blackwell) ----------------
static __device__ __forceinline__ unsigned long long pack2(float lo, float hi) {
    unsigned long long r;
    asm("mov.b64 %0, {%1,%2};" : "=l"(r) : "f"(lo), "f"(hi));
    return r;
}
static __device__ __forceinline__ float2 unpack2(unsigned long long v) {
    float2 r;
    asm("mov.b64 {%0,%1}, %2;" : "=f"(r.x), "=f"(r.y) : "l"(v));
    return r;
}
static __device__ __forceinline__ void fma2(unsigned long long& d,
                                            unsigned long long a,
                                            unsigned long long b) {
    asm("fma.rn.f32x2 %0, %1, %2, %0;" : "+l"(d) : "l"(a), "l"(b));
}

// ============================================================================
// Fused kernel: 256 blocks x 256 threads; block b owns rows 4b..4b+3.
// Phase P (pool): thread = (ch 0..127, nbr-half). One channel x all 64 k in
//   registers -> conv2 result per neighbor is complete per-thread: no k-half
//   combine, no partial smem traffic. h1 double-buffered -> 1 barrier/group.
//   Per-row pooled max lives in registers across all 4 rows; single combine
//   across nbr-halves at the end.
// Phase T (trunk): feat[132]->64->128->64->4 -> (a_x,a_y), f32x2 GEMV.
// ============================================================================

// ---- shared memory layout (bytes) ----
// Phase P:  s4 @0 [16384] | nbr @16384 [4][256]*4 | h1 @20480 [2][512]*4
//           comb @24576 [4][128]*4 | w1s @26624 [320]*4 | b1s @27904 [64]*4
// Phase T:  wP @0 u64[66*65]=34320 | w4 @34320 | bb1 @35344 | bb2 @35600 |
//           bb3 @36112 | b4s @36368
// Persist:  feat @36384 [4][132]*4 | cnt @38496 int[8]
#define SM_TOTAL 38528

__global__ __launch_bounds__(256, 2) void fused_kernel(
    const float* __restrict__ s, const float* __restrict__ g,
    const float* __restrict__ w1g, const float* __restrict__ b1g,
    const float* __restrict__ w2g, const float* __restrict__ b2g,
    const float* __restrict__ fc1w, const float* __restrict__ fc1b,
    const float* __restrict__ fc2w, const float* __restrict__ fc2b,
    const float* __restrict__ fc3w, const float* __restrict__ fc3b,
    const float* __restrict__ fc4w, const float* __restrict__ fc4b,
    float* __restrict__ out)
{
    __shared__ __align__(16) char smem_raw[SM_TOTAL];

    const int tid = threadIdx.x;

    // ======================= PHASE P: pool =======================
    float4* s4   = reinterpret_cast<float4*>(smem_raw);
    int (*nbr)[256] = reinterpret_cast<int(*)[256]>(smem_raw + 16384);
    float* h1    = reinterpret_cast<float*>(smem_raw + 20480);   // [2][512]
    float (*comb)[128] = reinterpret_cast<float(*)[128]>(smem_raw + 24576);
    float* w1s   = reinterpret_cast<float*>(smem_raw + 26624);
    float* b1s   = reinterpret_cast<float*>(smem_raw + 27904);
    float (*feat)[132] = reinterpret_cast<float(*)[132]>(smem_raw + 36384);
    int*   cnt   = reinterpret_cast<int*>(smem_raw + 38496);
    int*   cntp  = cnt + 4;

    const int ch  = tid & 127;        // conv2 output channel (full k)
    const int nnh = tid >> 7;         // neighbor half: nbrs {nnh*4 .. nnh*4+3}

    // conv2 weights: 1 channel x 64 k = 16 LDG.128 -> 32 f32x2 packs (64 regs)
    unsigned long long w2p[32];
    {
        const float4* wr = reinterpret_cast<const float4*>(w2g + ch * 64);
        float4 wv[16];
#pragma unroll
        for (int q = 0; q < 16; q++) wv[q] = wr[q];
#pragma unroll
        for (int q = 0; q < 16; q++) {
            w2p[2 * q]     = pack2(wv[q].x, wv[q].y);
            w2p[2 * q + 1] = pack2(wv[q].z, wv[q].w);
        }
    }
    const float b2 = b2g[ch];

    // stage s (4 batched LDG.128 each), w1, b1; reset counters
#pragma unroll
    for (int j = 0; j < 4; j++)
        s4[tid + 256 * j] = reinterpret_cast<const float4*>(s)[tid + 256 * j];
    for (int idx = tid; idx < 320; idx += 256) w1s[idx] = w1g[idx];
    if (tid < 64) b1s[tid] = b1g[tid];
    if (tid < 4)  cnt[tid] = 0;
    __syncthreads();

    const int   c1  = tid & 63;   // conv1 channel this thread computes
    const int   slb = tid >> 6;   // conv1 slot base (covers slb, slb+4)
    const float w1r0 = w1s[c1 * 5 + 0], w1r1 = w1s[c1 * 5 + 1],
                w1r2 = w1s[c1 * 5 + 2], w1r3 = w1s[c1 * 5 + 3],
                w1r4 = w1s[c1 * 5 + 4], b1r = b1s[c1];

    const int i0 = blockIdx.x * 4;
    float4 si[4];
#pragma unroll
    for (int rr = 0; rr < 4; rr++) si[rr] = s4[i0 + rr];

    // ---- one scan pass serves all 4 rows ----
    for (int j = tid; j < NPTS; j += 256) {
        float4 sj = s4[j];
#pragma unroll
        for (int rr = 0; rr < 4; rr++) {
            float dx = si[rr].x - sj.x, dy = si[rr].y - sj.y;
            if (dx * dx + dy * dy < 0.25f) {
                int pq = atomicAdd(&cnt[rr], 1);
                nbr[rr][pq] = j;
            }
        }
    }
    __syncthreads();
    if (tid < 4) {
        int c = cnt[tid], cp = (c + 7) & ~7;
        for (int t = c; t < cp; t++) nbr[tid][t] = i0 + tid;  // self-pad (idempotent)
        cntp[tid] = cp;
    }
    __syncthreads();

    // ---- pool: rows sequential, 8-nbr groups, ONE barrier per group ----
    float pooledr[4];
#pragma unroll
    for (int rr = 0; rr < 4; rr++) pooledr[rr] = 0.0f;  // max vs 0 covers mask & relu

    int buf = 0;
#pragma unroll
    for (int rr = 0; rr < 4; rr++) {
        const float4 sir = si[rr];
        const int    i   = i0 + rr;
        const int    cp  = cntp[rr];
        const int*   nb  = nbr[rr];
        float pooled = pooledr[rr];

        for (int n = 0; n < cp; n += 8, buf ^= 1) {
            float* h1w = h1 + buf * 512;

            // conv1: thread fills h1w[c1] for slots slb and slb+4
#pragma unroll
            for (int t = 0; t < 2; t++) {
                int sl = slb + 4 * t;
                int j  = nb[n + sl];
                float4 sj = s4[j];
                float dx = sir.x - sj.x, dy = sir.y - sj.y;
                float dz = sir.z - sj.z, dw = sir.w - sj.w;
                float ind = (j == i) ? 1.0f : 0.0f;
                float v = b1r;
                v = fmaf(dx, w1r0, v);
                v = fmaf(dy, w1r1, v);
                v = fmaf(dz, w1r2, v);
                v = fmaf(dw, w1r3, v);
                v = fmaf(ind, w1r4, v);
                h1w[sl * 64 + c1] = fmaxf(v, 0.0f);   // conflict-free
            }
            __syncthreads();
            // (writes to buf^1 happen next iteration, after every thread has
            //  finished reading buf^1 in the previous interval — 1 barrier safe)

            // conv2: this thread's 4 neighbors x 1 channel x all 64 k.
            // q-major: 4 independent acc chains, LDS.128 uniform broadcasts.
            const ulonglong2* hb0 = reinterpret_cast<const ulonglong2*>(h1w + (nnh * 4 + 0) * 64);
            const ulonglong2* hb1 = reinterpret_cast<const ulonglong2*>(h1w + (nnh * 4 + 1) * 64);
            const ulonglong2* hb2 = reinterpret_cast<const ulonglong2*>(h1w + (nnh * 4 + 2) * 64);
            const ulonglong2* hb3 = reinterpret_cast<const ulonglong2*>(h1w + (nnh * 4 + 3) * 64);
            unsigned long long a0 = 0ull, a1 = 0ull, a2 = 0ull, a3 = 0ull;
#pragma unroll
            for (int q = 0; q < 16; q++) {
                ulonglong2 h0 = hb0[q], h1v = hb1[q], h2 = hb2[q], h3 = hb3[q];
                fma2(a0, h0.x,  w2p[2 * q]);
                fma2(a1, h1v.x, w2p[2 * q]);
                fma2(a2, h2.x,  w2p[2 * q]);
                fma2(a3, h3.x,  w2p[2 * q]);
                fma2(a0, h0.y,  w2p[2 * q + 1]);
                fma2(a1, h1v.y, w2p[2 * q + 1]);
                fma2(a2, h2.y,  w2p[2 * q + 1]);
                fma2(a3, h3.y,  w2p[2 * q + 1]);
            }
            { float2 f = unpack2(a0); pooled = fmaxf(pooled, f.x + f.y + b2); }
            { float2 f = unpack2(a1); pooled = fmaxf(pooled, f.x + f.y + b2); }
            { float2 f = unpack2(a2); pooled = fmaxf(pooled, f.x + f.y + b2); }
            { float2 f = unpack2(a3); pooled = fmaxf(pooled, f.x + f.y + b2); }
        }
        pooledr[rr] = pooled;
    }

    // ---- combine the two neighbor-halves (single reduce for all 4 rows) ----
    __syncthreads();
    if (nnh == 1) {
#pragma unroll
        for (int rr = 0; rr < 4; rr++) comb[rr][ch] = pooledr[rr];
    }
    __syncthreads();
    if (nnh == 0) {
#pragma unroll
        for (int rr = 0; rr < 4; rr++)
            feat[rr][ch] = fmaxf(pooledr[rr], comb[rr][ch]);
    }
    __syncthreads();   // P-phase smem dead; safe to overlay T-phase data

    // ======================= PHASE T: trunk =======================
    unsigned long long* wP = reinterpret_cast<unsigned long long*>(smem_raw);
    float* w4  = reinterpret_cast<float*>(smem_raw + 34320);
    float* bb1 = reinterpret_cast<float*>(smem_raw + 35344);
    float* bb2 = reinterpret_cast<float*>(smem_raw + 35600);
    float* bb3 = reinterpret_cast<float*>(smem_raw + 36112);
    float* b4s = reinterpret_cast<float*>(smem_raw + 36368);
    float (*act)[132] = feat;   // same storage

    const int lane   = tid & 31;
    const int w      = tid >> 5;
    const bool active = (w < 4);
    const int r      = i0 + (active ? w : 0);

    float4 sv = make_float4(0.f, 0.f, 0.f, 0.f);
    float2 gv = make_float2(0.f, 0.f);
    if (active) {
        sv = reinterpret_cast<const float4*>(s)[r];
        gv = reinterpret_cast<const float2*>(g)[r];
        if (lane == 0) {
            act[w][128] = sv.x - gv.x;
            act[w][129] = sv.y - gv.y;
            act[w][130] = sv.z;
            act[w][131] = sv.w;
        }
    }

    // fc1 staging loads: 2112 float4, register-buffered
    const float4* f1w4 = reinterpret_cast<const float4*>(fc1w);
    float4 v1[8];
#pragma unroll
    for (int rr = 0; rr < 8; rr++) v1[rr] = f1w4[tid + 256 * rr];
    float4 v1x;
    if (tid < 64) v1x = f1w4[2048 + tid];

    // biases + fc4
    if (tid < 64)  bb1[tid] = fc1b[tid];
    if (tid < 128) bb2[tid] = fc2b[tid];
    if (tid >= 128 && tid < 192) bb3[tid - 128] = fc3b[tid - 128];
    if (tid < 4)   b4s[tid] = fc4b[tid];
    if (tid < 64) {                       // fc4: 64 float4s
        float4 v = reinterpret_cast<const float4*>(fc4w)[tid];
        int o = tid >> 4;
        int k = (tid << 2) & 63;
        w4[(k + 0) * 4 + o] = v.x; w4[(k + 1) * 4 + o] = v.y;
        w4[(k + 2) * 4 + o] = v.z; w4[(k + 3) * 4 + o] = v.w;
    }

    // STS fc1 as k-pair u64: wP[k2*65 + o]
#pragma unroll
    for (int rr = 0; rr < 8; rr++) {
        int e = (tid + 256 * rr) << 2;
        int o = e / 132;                  // 132 % 4 == 0: no row straddle
        int k = e - o * 132;
        int k2 = k >> 1;
        wP[(k2 + 0) * 65 + o] = pack2(v1[rr].x, v1[rr].y);
        wP[(k2 + 1) * 65 + o] = pack2(v1[rr].z, v1[rr].w);
    }
    if (tid < 64) {
        int e = (2048 + tid) << 2;
        int o = e / 132;
        int k = e - o * 132;
        int k2 = k >> 1;
        wP[(k2 + 0) * 65 + o] = pack2(v1x.x, v1x.y);
        wP[(k2 + 1) * 65 + o] = pack2(v1x.z, v1x.w);
    }
    __syncthreads();

    // prefetch fc2 before L1 compute
    const float4* f2w4 = reinterpret_cast<const float4*>(fc2w);
    float4 v2[8];
#pragma unroll
    for (int rr = 0; rr < 8; rr++) v2[rr] = f2w4[tid + 256 * rr];

    // L1: 132 -> 64
    {
        float a0 = 0.f, a1 = 0.f;
        if (active) {
            const unsigned long long* actp =
                reinterpret_cast<const unsigned long long*>(act[w]);
            unsigned long long a0p = 0ull, a1p = 0ull;
#pragma unroll 6
            for (int k2 = 0; k2 < 66; k2++) {
                unsigned long long ap = actp[k2];
                fma2(a0p, ap, wP[k2 * 65 + lane]);
                fma2(a1p, ap, wP[k2 * 65 + lane + 32]);
            }
            float2 f0 = unpack2(a0p), f1 = unpack2(a1p);
            a0 = fmaxf(f0.x + f0.y + bb1[lane], 0.0f);
            a1 = fmaxf(f1.x + f1.y + bb1[lane + 32], 0.0f);
        }
        __syncthreads();
        if (active) { act[w][lane] = a0; act[w][lane + 32] = a1; }
    }

    // STS fc2: [128][64] -> wP[k2*129 + o]
#pragma unroll
    for (int rr = 0; rr < 8; rr++) {
        int e = (tid + 256 * rr) << 2;
        int o = e >> 6;
        int k = e & 63;
        int k2 = k >> 1;
        wP[(k2 + 0) * 129 + o] = pack2(v2[rr].x, v2[rr].y);
        wP[(k2 + 1) * 129 + o] = pack2(v2[rr].z, v2[rr].w);
    }
    __syncthreads();

    // prefetch fc3 before L2 compute
    const float4* f3w4 = reinterpret_cast<const float4*>(fc3w);
    float4 v3[8];
#pragma unroll
    for (int rr = 0; rr < 8; rr++) v3[rr] = f3w4[tid + 256 * rr];

    // L2: 64 -> 128
    {
        float o0 = 0.f, o1 = 0.f, o2 = 0.f, o3 = 0.f;
        if (active) {
            const unsigned long long* actp =
                reinterpret_cast<const unsigned long long*>(act[w]);
            unsigned long long ac[4] = {0ull, 0ull, 0ull, 0ull};
#pragma unroll 4
            for (int k2 = 0; k2 < 32; k2++) {
                unsigned long long ap = actp[k2];
                fma2(ac[0], ap, wP[k2 * 129 + lane]);
                fma2(ac[1], ap, wP[k2 * 129 + lane + 32]);
                fma2(ac[2], ap, wP[k2 * 129 + lane + 64]);
                fma2(ac[3], ap, wP[k2 * 129 + lane + 96]);
            }
            { float2 f = unpack2(ac[0]); o0 = fmaxf(f.x + f.y + bb2[lane],      0.0f); }
            { float2 f = unpack2(ac[1]); o1 = fmaxf(f.x + f.y + bb2[lane + 32], 0.0f); }
            { float2 f = unpack2(ac[2]); o2 = fmaxf(f.x + f.y + bb2[lane + 64], 0.0f); }
            { float2 f = unpack2(ac[3]); o3 = fmaxf(f.x + f.y + bb2[lane + 96], 0.0f); }
        }
        __syncthreads();
        if (active) {
            act[w][lane] = o0; act[w][lane + 32] = o1;
            act[w][lane + 64] = o2; act[w][lane + 96] = o3;
        }
    }

    // STS fc3: [64][128] -> wP[k2*65 + o]
#pragma unroll
    for (int rr = 0; rr < 8; rr++) {
        int e = (tid + 256 * rr) << 2;
        int o = e >> 7;
        int k = e & 127;
        int k2 = k >> 1;
        wP[(k2 + 0) * 65 + o] = pack2(v3[rr].x, v3[rr].y);
        wP[(k2 + 1) * 65 + o] = pack2(v3[rr].z, v3[rr].w);
    }
    __syncthreads();

    if (active) {
        // L3: 128 -> 64 (warp-private from here on)
        const unsigned long long* actp =
            reinterpret_cast<const unsigned long long*>(act[w]);
        unsigned long long a0p = 0ull, a1p = 0ull;
#pragma unroll 8
        for (int k2 = 0; k2 < 64; k2++) {
            unsigned long long ap = actp[k2];
            fma2(a0p, ap, wP[k2 * 65 + lane]);
            fma2(a1p, ap, wP[k2 * 65 + lane + 32]);
        }
        float2 f0 = unpack2(a0p), f1 = unpack2(a1p);
        float a0 = fmaxf(f0.x + f0.y + bb3[lane], 0.0f);
        float a1 = fmaxf(f1.x + f1.y + bb3[lane + 32], 0.0f);
        __syncwarp();
        act[w][lane] = a0; act[w][lane + 32] = a1;
        __syncwarp();

        // L4: 64 -> 4, sigmoid, gains
        int ol = lane & 3;
        float acc = b4s[ol];
#pragma unroll 4
        for (int k = 0; k < 64; k++)
            acc = fmaf(act[w][k], w4[k * 4 + ol], acc);
        float kv = 2.0f / (1.0f + expf(-acc)) - 1.0f;

        float k1 = __shfl_sync(0xffffffffu, kv, 0);
        float k2 = __shfl_sync(0xffffffffu, kv, 1);
        float k3 = __shfl_sync(0xffffffffu, kv, 2);
        float k4 = __shfl_sync(0xffffffffu, kv, 3);

        if (lane == 0) {
            float sg0 = sv.x - gv.x;
            float sg1 = sv.y - gv.y;
            out[r * 2 + 0] = -(k1 * sg0 + k2 * sv.z);
            out[r * 2 + 1] = -(k3 * sg1 + k4 * sv.w);
        }
    }
}

// ============================================================================
extern "C" void kernel_launch(void* const* d_in, const int* in_sizes, int n_in,
                              void* d_out, int out_size)
{
    const float* s    = (const float*)d_in[0];
    const float* g    = (const float*)d_in[1];
    const float* c1w  = (const float*)d_in[2];
    const float* c1b  = (const float*)d_in[3];
    const float* c2w  = (const float*)d_in[4];
    const float* c2b  = (const float*)d_in[5];
    const float* f1w  = (const float*)d_in[6];
    const float* f1b  = (const float*)d_in[7];
    const float* f2w  = (const float*)d_in[8];
    const float* f2b  = (const float*)d_in[9];
    const float* f3w  = (const float*)d_in[10];
    const float* f3b  = (const float*)d_in[11];
    const float* f4w  = (const float*)d_in[12];
    const float* f4b  = (const float*)d_in[13];
    float* out = (float*)d_out;

    fused_kernel<<<NPTS / 4, 256>>>(s, g, c1w, c1b, c2w, c2b,
                                    f1w, f1b, f2w, f2b, f3w, f3b,
                                    f4w, f4b, out);
}